// round 3
// baseline (speedup 1.0000x reference)
#include <cuda_runtime.h>
#include <cuda_bf16.h>
#include <math.h>

#define N_NODES   50000
#define C         128      // IN_C == HID
#define C4        32       // 128 floats = 32 float4
#define LIN       256
#define NCLS      10
#define NGRAPH    512

// ---------------- scratch (float4-typed => 16B-aligned) -----------------------
__device__ float4 g_t4  [N_NODES * C4];   // t = h @ W
__device__ float4 g_agg4[N_NODES * C4];   // aggregated output
__device__ float4 g_h4  [N_NODES * C4];   // relu(agg + b) -> next layer input
__device__ float  g_deg [N_NODES];
__device__ float  g_dinv[N_NODES];
__device__ float4 g_pool4[NGRAPH * C4];
__device__ float  g_cnt  [NGRAPH];
__device__ int    g_is64;                 // 1 if index buffers are int64

// ---------------- dtype detection --------------------------------------------
// Node ids < 50000 < 2^31. If buffer is little-endian int64, every odd int32
// is 0. Genuine int32 edge data has random ids at odd positions (all-zero
// probability ~ (1/50000)^64 ~= 0). Reading 128 int32 = 512B is within the
// buffer under either interpretation (buffer >= 3.2M elements * 4B).
__global__ void k_detect(const int* __restrict__ ei32) {
    if (threadIdx.x == 0 && blockIdx.x == 0) {
        int is64 = 1;
        for (int i = 1; i < 128; i += 2)
            if (ei32[i] != 0) { is64 = 0; break; }
        g_is64 = is64;
    }
}

__device__ __forceinline__ int load_idx(const void* p, long long i) {
    if (g_is64) return (int)((const long long*)p)[i];
    return ((const int*)p)[i];
}

// ---------------- degree / norm ----------------------------------------------
__global__ void k_deg_init(int n) {
    int i = blockIdx.x * blockDim.x + threadIdx.x;
    if (i < n) g_deg[i] = 1.0f;            // self-loop
}

__global__ void k_deg_edges(const void* __restrict__ ei, int E, int n) {
    int e = blockIdx.x * blockDim.x + threadIdx.x;
    if (e < E) {
        int c = load_idx(ei, (long long)E + e);   // col
        if ((unsigned)c < (unsigned)n) atomicAdd(&g_deg[c], 1.0f);
    }
}

__global__ void k_dinv(int n) {
    int i = blockIdx.x * blockDim.x + threadIdx.x;
    if (i < n) g_dinv[i] = rsqrtf(g_deg[i]);
}

// ---------------- GEMM: T = X @ W, AGG = T * dinv^2 (self-loop init) ---------
__global__ void k_gemm_selfloop(const float* __restrict__ X,
                                const float* __restrict__ W,
                                int n, int use_gh) {
    __shared__ float xs[8][C];
    const float* src = use_gh ? (const float*)g_h4 : X;
    int r0 = blockIdx.x * 8;
    int tid = threadIdx.x;
    for (int i = tid; i < 8 * C; i += 256) {
        int rr = i >> 7, cc = i & 127;
        int r = r0 + rr;
        xs[rr][cc] = (r < n) ? src[r * C + cc] : 0.0f;
    }
    __syncthreads();
    int lrow = tid >> 5;
    int lane = tid & 31;
    int r = r0 + lrow;
    if (r >= n) return;

    const float4* W4 = (const float4*)W;
    float4 acc = make_float4(0.f, 0.f, 0.f, 0.f);
    #pragma unroll
    for (int k = 0; k < C; k++) {
        float xv = xs[lrow][k];
        float4 w = W4[k * C4 + lane];
        acc.x += xv * w.x; acc.y += xv * w.y;
        acc.z += xv * w.z; acc.w += xv * w.w;
    }
    g_t4[r * C4 + lane] = acc;
    float s = g_dinv[r]; s = s * s;
    g_agg4[r * C4 + lane] = make_float4(acc.x * s, acc.y * s, acc.z * s, acc.w * s);
}

// ---------------- edge scatter: AGG[col] += T[row] * dinv[row]*dinv[col] -----
// one warp per edge; lane handles one float4 (4 channels); HW float4 REDs.
__global__ void k_scatter(const void* __restrict__ ei, int E, int n) {
    long long gid = (long long)blockIdx.x * blockDim.x + threadIdx.x;
    int e = (int)(gid >> 5);
    int lane = threadIdx.x & 31;
    if (e >= E) return;
    int r = load_idx(ei, e);
    int c = load_idx(ei, (long long)E + e);
    if ((unsigned)r >= (unsigned)n || (unsigned)c >= (unsigned)n) return;
    float nm = g_dinv[r] * g_dinv[c];
    float4 v = g_t4[r * C4 + lane];
    float4 w = make_float4(v.x * nm, v.y * nm, v.z * nm, v.w * nm);
    atomicAdd(&g_agg4[c * C4 + lane], w);
}

// ---------------- bias + relu: H = relu(AGG + b) ------------------------------
__global__ void k_bias_relu(const float* __restrict__ b, int n) {
    int i = blockIdx.x * blockDim.x + threadIdx.x;
    if (i < n * C) {
        float v = ((const float*)g_agg4)[i] + b[i & 127];
        ((float*)g_h4)[i] = v > 0.f ? v : 0.f;
    }
}

// ---------------- pooling -----------------------------------------------------
__global__ void k_pool_init() {
    int i = blockIdx.x * blockDim.x + threadIdx.x;
    if (i < NGRAPH * C4) g_pool4[i] = make_float4(0.f, 0.f, 0.f, 0.f);
    if (i < NGRAPH)      g_cnt[i]  = 0.f;
}

__global__ void k_pool(const void* __restrict__ batch, int n) {
    long long gid = (long long)blockIdx.x * blockDim.x + threadIdx.x;
    int node = (int)(gid >> 5);
    int lane = threadIdx.x & 31;
    if (node >= n) return;
    int b = load_idx(batch, node);
    if ((unsigned)b >= NGRAPH) return;
    float4 v = g_h4[node * C4 + lane];
    atomicAdd(&g_pool4[b * C4 + lane], v);
    if (lane == 0) atomicAdd(&g_cnt[b], 1.0f);
}

// ---------------- head: mean -> lin1+relu -> lin2 -> log_softmax -------------
__global__ void k_head(const float* __restrict__ lin1_w,
                       const float* __restrict__ lin1_b,
                       const float* __restrict__ lin2_w,
                       const float* __restrict__ lin2_b,
                       float* __restrict__ out) {
    __shared__ float p[C];
    __shared__ float z1[LIN];
    __shared__ float z2[NCLS];
    int g = blockIdx.x;
    int tid = threadIdx.x;
    float cnt = g_cnt[g];
    if (cnt < 1.f) cnt = 1.f;
    if (tid < C) p[tid] = ((const float*)g_pool4)[g * C + tid] / cnt;
    __syncthreads();

    float acc = lin1_b[tid];
    #pragma unroll
    for (int k = 0; k < C; k++) acc += p[k] * lin1_w[k * LIN + tid];
    z1[tid] = acc > 0.f ? acc : 0.f;
    __syncthreads();

    if (tid < NCLS) {
        float a = lin2_b[tid];
        for (int j = 0; j < LIN; j++) a += z1[j] * lin2_w[j * NCLS + tid];
        z2[tid] = a;
    }
    __syncthreads();

    if (tid == 0) {
        float m = z2[0];
        #pragma unroll
        for (int k = 1; k < NCLS; k++) m = fmaxf(m, z2[k]);
        float s = 0.f;
        #pragma unroll
        for (int k = 0; k < NCLS; k++) s += expf(z2[k] - m);
        float lse = m + logf(s);
        #pragma unroll
        for (int k = 0; k < NCLS; k++) out[g * NCLS + k] = z2[k] - lse;
    }
}

__global__ void k_zero_out(float* out, int n) {
    int i = blockIdx.x * blockDim.x + threadIdx.x;
    if (i < n) out[i] = 0.f;
}

// ---------------- launch ------------------------------------------------------
extern "C" void kernel_launch(void* const* d_in, const int* in_sizes, int n_in,
                              void* d_out, int out_size) {
    const float* x      = (const float*)d_in[0];
    const void*  ei     = d_in[1];
    const void*  batch  = d_in[2];
    const float* W1     = (const float*)d_in[3];
    const float* b1     = (const float*)d_in[4];
    const float* W2     = (const float*)d_in[5];
    const float* b2     = (const float*)d_in[6];
    const float* W3     = (const float*)d_in[7];
    const float* b3     = (const float*)d_in[8];
    const float* lin1_w = (const float*)d_in[9];
    const float* lin1_b = (const float*)d_in[10];
    const float* lin2_w = (const float*)d_in[11];
    const float* lin2_b = (const float*)d_in[12];
    float* out = (float*)d_out;

    const int n = in_sizes[0] / C;          // 50000
    const int E = in_sizes[1] / 2;          // 1600000

    k_detect<<<1, 32>>>((const int*)ei);

    // degree + dinv
    k_deg_init<<<(n + 255) / 256, 256>>>(n);
    k_deg_edges<<<(E + 255) / 256, 256>>>(ei, E, n);
    k_dinv<<<(n + 255) / 256, 256>>>(n);

    const int gemm_blocks = (n + 7) / 8;
    const long long scat_threads = (long long)E * 32;
    const int scat_blocks = (int)((scat_threads + 255) / 256);
    const int er_blocks = (n * C + 255) / 256;

    const float* Ws[3] = { W1, W2, W3 };
    const float* bs[3] = { b1, b2, b3 };
    for (int l = 0; l < 3; l++) {
        k_gemm_selfloop<<<gemm_blocks, 256>>>(x, Ws[l], n, l > 0 ? 1 : 0);
        k_scatter<<<scat_blocks, 256>>>(ei, E, n);
        k_bias_relu<<<er_blocks, 256>>>(bs[l], n);
    }

    // pooling
    k_pool_init<<<(NGRAPH * C + 255) / 256, 256>>>();
    k_pool<<<(int)(((long long)n * 32 + 255) / 256), 256>>>(batch, n);

    // head (+ zero-fill entire out first so any trailing elements are 0)
    k_zero_out<<<(out_size + 255) / 256, 256>>>(out, out_size);
    k_head<<<NGRAPH, LIN>>>(lin1_w, lin1_b, lin2_w, lin2_b, out);
}

// round 4
// speedup vs baseline: 1.6841x; 1.6841x over previous
#include <cuda_runtime.h>
#include <cuda_bf16.h>
#include <math.h>

#define N_NODES   50000
#define MAX_E     1700000
#define C         128      // IN_C == HID
#define C4        32       // 128 floats = 32 float4
#define LIN       256
#define NCLS      10
#define NGRAPH    512

// ---------------- scratch -----------------------------------------------------
__device__ float4 g_t4 [N_NODES * C4];    // t' = (h @ W) * dinv[row]
__device__ float4 g_h4 [N_NODES * C4];    // relu(agg*dinv + b)
__device__ float  g_dinv[N_NODES];
__device__ int    g_degi[N_NODES];        // edge-only in-degree
__device__ int    g_off [N_NODES + 1];    // CSR offsets
__device__ int    g_cur [N_NODES];        // fill cursors
__device__ int    g_csr [MAX_E];          // CSR row ids (sources), grouped by col
__device__ int    g_batch[N_NODES];       // int32 batch ids
__device__ float4 g_pool4[NGRAPH * C4];
__device__ float  g_cnt  [NGRAPH];
__device__ int    g_is64;

// ---------------- dtype detection --------------------------------------------
// ids < 50000 < 2^31: little-endian int64 => every odd int32 word is 0.
__global__ void k_detect(const int* __restrict__ ei32) {
    if (threadIdx.x == 0 && blockIdx.x == 0) {
        int is64 = 1;
        for (int i = 1; i < 128; i += 2)
            if (ei32[i] != 0) { is64 = 0; break; }
        g_is64 = is64;
    }
}

__device__ __forceinline__ int load_idx(const void* p, long long i) {
    if (g_is64) return (int)((const long long*)p)[i];
    return ((const int*)p)[i];
}

// ---------------- prep --------------------------------------------------------
__global__ void k_zero_prep(int n) {
    int i = blockIdx.x * blockDim.x + threadIdx.x;
    if (i < n) g_degi[i] = 0;
    if (i < NGRAPH * C4) g_pool4[i] = make_float4(0.f, 0.f, 0.f, 0.f);
    if (i < NGRAPH)      g_cnt[i]  = 0.f;
}

__global__ void k_deg_edges(const void* __restrict__ ei, int E, int n) {
    int e = blockIdx.x * blockDim.x + threadIdx.x;
    if (e < E) {
        int c = load_idx(ei, (long long)E + e);
        if ((unsigned)c < (unsigned)n) atomicAdd(&g_degi[c], 1);
    }
}

// single-block chunked Hillis-Steele scan -> exclusive offsets + cursors
__global__ void k_scan(int n) {
    __shared__ int sh[1024];
    __shared__ int carry;
    if (threadIdx.x == 0) carry = 0;
    __syncthreads();
    for (int base = 0; base < n; base += 1024) {
        int i = base + (int)threadIdx.x;
        int v = (i < n) ? g_degi[i] : 0;
        sh[threadIdx.x] = v;
        __syncthreads();
        for (int off = 1; off < 1024; off <<= 1) {
            int t = (threadIdx.x >= off) ? sh[threadIdx.x - off] : 0;
            __syncthreads();
            sh[threadIdx.x] += t;
            __syncthreads();
        }
        int excl = sh[threadIdx.x] - v + carry;
        if (i < n) { g_off[i] = excl; g_cur[i] = excl; }
        __syncthreads();
        if (threadIdx.x == 1023) carry += sh[1023];
        __syncthreads();
    }
    if (threadIdx.x == 0) g_off[n] = carry;
}

__global__ void k_fill(const void* __restrict__ ei, int E, int n) {
    int e = blockIdx.x * blockDim.x + threadIdx.x;
    if (e >= E) return;
    int r = load_idx(ei, e);
    int c = load_idx(ei, (long long)E + e);
    if ((unsigned)r >= (unsigned)n || (unsigned)c >= (unsigned)n) return;
    int pos = atomicAdd(&g_cur[c], 1);
    g_csr[pos] = r;
}

// dinv (+1 self loop), int32 batch, graph counts
__global__ void k_node_prep(const void* __restrict__ batch, int n) {
    int i = blockIdx.x * blockDim.x + threadIdx.x;
    if (i >= n) return;
    g_dinv[i] = rsqrtf((float)(g_degi[i] + 1));
    int b = load_idx(batch, i);
    if ((unsigned)b >= NGRAPH) b = 0;
    g_batch[i] = b;
    atomicAdd(&g_cnt[b], 1.0f);
}

// ---------------- GEMM: T' = (X @ W) * dinv[row] ------------------------------
__global__ void k_gemm(const float* __restrict__ X,
                       const float* __restrict__ W,
                       int n, int use_gh) {
    __shared__ float xs[8][C];
    const float* src = use_gh ? (const float*)g_h4 : X;
    int r0 = blockIdx.x * 8;
    int tid = threadIdx.x;
    for (int i = tid; i < 8 * C; i += 256) {
        int rr = i >> 7, cc = i & 127;
        int r = r0 + rr;
        xs[rr][cc] = (r < n) ? src[r * C + cc] : 0.0f;
    }
    __syncthreads();
    int lrow = tid >> 5;
    int lane = tid & 31;
    int r = r0 + lrow;
    if (r >= n) return;

    const float4* W4 = (const float4*)W;
    float4 acc = make_float4(0.f, 0.f, 0.f, 0.f);
    #pragma unroll
    for (int k = 0; k < C; k++) {
        float xv = xs[lrow][k];
        float4 w = W4[k * C4 + lane];
        acc.x += xv * w.x; acc.y += xv * w.y;
        acc.z += xv * w.z; acc.w += xv * w.w;
    }
    float di = g_dinv[r];
    g_t4[r * C4 + lane] = make_float4(acc.x * di, acc.y * di, acc.z * di, acc.w * di);
}

// ---------------- CSR gather: h[c] = relu((t'[c] + sum t'[row]) * dinv[c] + b)
// one warp per node; lane owns one float4 (4 channels); unroll 4 for MLP.
__global__ void k_gather(const float* __restrict__ bias, int n, int pool_mode) {
    int node = blockIdx.x * 8 + (threadIdx.x >> 5);
    int lane = threadIdx.x & 31;
    if (node >= n) return;
    int s = g_off[node], e = g_off[node + 1];

    float4 acc = g_t4[node * C4 + lane];   // self-loop term (t'[c])
    int i = s;
    for (; i + 4 <= e; i += 4) {
        int r0 = g_csr[i], r1 = g_csr[i + 1], r2 = g_csr[i + 2], r3 = g_csr[i + 3];
        float4 a = g_t4[r0 * C4 + lane];
        float4 b4 = g_t4[r1 * C4 + lane];
        float4 c4 = g_t4[r2 * C4 + lane];
        float4 d4 = g_t4[r3 * C4 + lane];
        acc.x += (a.x + b4.x) + (c4.x + d4.x);
        acc.y += (a.y + b4.y) + (c4.y + d4.y);
        acc.z += (a.z + b4.z) + (c4.z + d4.z);
        acc.w += (a.w + b4.w) + (c4.w + d4.w);
    }
    for (; i < e; i++) {
        float4 a = g_t4[g_csr[i] * C4 + lane];
        acc.x += a.x; acc.y += a.y; acc.z += a.z; acc.w += a.w;
    }
    float di = g_dinv[node];
    float4 bv = ((const float4*)bias)[lane];
    float4 o;
    o.x = fmaxf(acc.x * di + bv.x, 0.f);
    o.y = fmaxf(acc.y * di + bv.y, 0.f);
    o.z = fmaxf(acc.z * di + bv.z, 0.f);
    o.w = fmaxf(acc.w * di + bv.w, 0.f);

    if (pool_mode) {
        int b = g_batch[node];
        atomicAdd(&g_pool4[b * C4 + lane], o);
    } else {
        g_h4[node * C4 + lane] = o;
    }
}

// ---------------- head: mean -> lin1+relu -> lin2 -> log_softmax -------------
__global__ void k_head(const float* __restrict__ lin1_w,
                       const float* __restrict__ lin1_b,
                       const float* __restrict__ lin2_w,
                       const float* __restrict__ lin2_b,
                       float* __restrict__ out) {
    __shared__ float p[C];
    __shared__ float z1[LIN];
    __shared__ float z2[NCLS];
    int g = blockIdx.x;
    int tid = threadIdx.x;
    float cnt = g_cnt[g];
    if (cnt < 1.f) cnt = 1.f;
    if (tid < C) p[tid] = ((const float*)g_pool4)[g * C + tid] / cnt;
    __syncthreads();

    float acc = lin1_b[tid];
    #pragma unroll
    for (int k = 0; k < C; k++) acc += p[k] * lin1_w[k * LIN + tid];
    z1[tid] = acc > 0.f ? acc : 0.f;
    __syncthreads();

    if (tid < NCLS) {
        float a = lin2_b[tid];
        for (int j = 0; j < LIN; j++) a += z1[j] * lin2_w[j * NCLS + tid];
        z2[tid] = a;
    }
    __syncthreads();

    if (tid == 0) {
        float m = z2[0];
        #pragma unroll
        for (int k = 1; k < NCLS; k++) m = fmaxf(m, z2[k]);
        float s = 0.f;
        #pragma unroll
        for (int k = 0; k < NCLS; k++) s += expf(z2[k] - m);
        float lse = m + logf(s);
        #pragma unroll
        for (int k = 0; k < NCLS; k++) out[g * NCLS + k] = z2[k] - lse;
    }
}

__global__ void k_zero_out(float* out, int n) {
    int i = blockIdx.x * blockDim.x + threadIdx.x;
    if (i < n) out[i] = 0.f;
}

// ---------------- launch ------------------------------------------------------
extern "C" void kernel_launch(void* const* d_in, const int* in_sizes, int n_in,
                              void* d_out, int out_size) {
    const float* x      = (const float*)d_in[0];
    const void*  ei     = d_in[1];
    const void*  batch  = d_in[2];
    const float* W1     = (const float*)d_in[3];
    const float* b1     = (const float*)d_in[4];
    const float* W2     = (const float*)d_in[5];
    const float* b2     = (const float*)d_in[6];
    const float* W3     = (const float*)d_in[7];
    const float* b3     = (const float*)d_in[8];
    const float* lin1_w = (const float*)d_in[9];
    const float* lin1_b = (const float*)d_in[10];
    const float* lin2_w = (const float*)d_in[11];
    const float* lin2_b = (const float*)d_in[12];
    float* out = (float*)d_out;

    const int n = in_sizes[0] / C;          // 50000
    const int E = in_sizes[1] / 2;          // 1600000

    k_detect<<<1, 32>>>((const int*)ei);

    // ---- CSR build + node prep (once per call) ----
    k_zero_prep<<<(n + 255) / 256, 256>>>(n);
    k_deg_edges<<<(E + 255) / 256, 256>>>(ei, E, n);
    k_scan<<<1, 1024>>>(n);
    k_fill<<<(E + 255) / 256, 256>>>(ei, E, n);
    k_node_prep<<<(n + 255) / 256, 256>>>(batch, n);

    // ---- 3 GCN layers ----
    const int gemm_blocks = (n + 7) / 8;
    const int gath_blocks = (n + 7) / 8;
    const float* Ws[3] = { W1, W2, W3 };
    const float* bs[3] = { b1, b2, b3 };
    for (int l = 0; l < 3; l++) {
        k_gemm<<<gemm_blocks, 256>>>(x, Ws[l], n, l > 0 ? 1 : 0);
        k_gather<<<gath_blocks, 256>>>(bs[l], n, l == 2 ? 1 : 0);
    }

    // ---- head ----
    k_zero_out<<<(out_size + 255) / 256, 256>>>(out, out_size);
    k_head<<<NGRAPH, LIN>>>(lin1_w, lin1_b, lin2_w, lin2_b, out);
}

// round 7
// speedup vs baseline: 2.0792x; 1.2346x over previous
#include <cuda_runtime.h>
#include <cuda_fp16.h>
#include <math.h>

#define N_NODES   50000
#define MAX_E     1700000
#define C         128      // IN_C == HID
#define C4        32       // 128 floats = 32 float4
#define LIN       256
#define NCLS      10
#define NGRAPH    512
#define SCAN_BS   1024
#define SCAN_NB   ((N_NODES + SCAN_BS - 1) / SCAN_BS)   // 49

// ---------------- scratch -----------------------------------------------------
__device__ uint2  g_t2h[N_NODES * C4];    // t' = (h @ W)*dinv[row], 4 halves/lane
__device__ float4 g_h4 [N_NODES * C4];    // relu(agg*dinv + b), fp32
__device__ float  g_dinv[N_NODES];
__device__ int    g_degi[N_NODES];        // edge-only in-degree
__device__ int    g_off [N_NODES + 1];    // CSR offsets
__device__ int    g_cur [N_NODES];        // fill cursors
__device__ int    g_csr [MAX_E];          // CSR row ids (sources), grouped by col
__device__ int    g_batch[N_NODES];       // int32 batch ids
__device__ float4 g_pool4[NGRAPH * C4];
__device__ float  g_cnt  [NGRAPH];
__device__ int    g_bsum [SCAN_NB];       // scan block totals
__device__ int    g_boff [SCAN_NB];       // scanned block offsets
__device__ int    g_is64;

// ---------------- dtype detection --------------------------------------------
// ids < 50000 < 2^31: little-endian int64 => every odd int32 word is 0.
__global__ void k_detect(const int* __restrict__ ei32) {
    if (threadIdx.x == 0 && blockIdx.x == 0) {
        int is64 = 1;
        for (int i = 1; i < 128; i += 2)
            if (ei32[i] != 0) { is64 = 0; break; }
        g_is64 = is64;
    }
}

__device__ __forceinline__ int load_idx(const void* p, long long i) {
    if (g_is64) return (int)((const long long*)p)[i];
    return ((const int*)p)[i];
}

// ---------------- prep --------------------------------------------------------
__global__ void k_zero_prep(int n) {
    int i = blockIdx.x * blockDim.x + threadIdx.x;
    if (i < n) g_degi[i] = 0;
    if (i < NGRAPH * C4) g_pool4[i] = make_float4(0.f, 0.f, 0.f, 0.f);
    if (i < NGRAPH)      g_cnt[i]  = 0.f;
}

__global__ void k_deg_edges(const void* __restrict__ ei, int E, int n) {
    int e = blockIdx.x * blockDim.x + threadIdx.x;
    if (e < E) {
        int c = load_idx(ei, (long long)E + e);
        if ((unsigned)c < (unsigned)n) atomicAdd(&g_degi[c], 1);
    }
}

// ---- 3-phase scan: block scan -> scan of block sums -> add offsets ----------
__global__ void k_scan1(int n) {
    __shared__ int sh[SCAN_BS];
    int i = blockIdx.x * SCAN_BS + threadIdx.x;
    int v = (i < n) ? g_degi[i] : 0;
    sh[threadIdx.x] = v;
    __syncthreads();
    #pragma unroll 1
    for (int off = 1; off < SCAN_BS; off <<= 1) {
        int t = (threadIdx.x >= off) ? sh[threadIdx.x - off] : 0;
        __syncthreads();
        sh[threadIdx.x] += t;
        __syncthreads();
    }
    if (i < n) g_off[i] = sh[threadIdx.x] - v;   // block-local exclusive prefix
    if (threadIdx.x == SCAN_BS - 1) g_bsum[blockIdx.x] = sh[SCAN_BS - 1];
}

__global__ void k_scan2() {
    __shared__ int sh[64];
    int v = (threadIdx.x < SCAN_NB) ? g_bsum[threadIdx.x] : 0;
    sh[threadIdx.x] = v;
    __syncthreads();
    #pragma unroll 1
    for (int off = 1; off < 64; off <<= 1) {
        int t = (threadIdx.x >= off) ? sh[threadIdx.x - off] : 0;
        __syncthreads();
        sh[threadIdx.x] += t;
        __syncthreads();
    }
    if (threadIdx.x < SCAN_NB) g_boff[threadIdx.x] = sh[threadIdx.x] - v;  // exclusive
}

__global__ void k_scan3(int n) {
    int i = blockIdx.x * blockDim.x + threadIdx.x;
    if (i < n) {
        int o = g_off[i] + g_boff[i >> 10];
        g_off[i] = o;
        g_cur[i] = o;
    }
    if (i == n) {
        g_off[n] = g_boff[SCAN_NB - 1] + g_bsum[SCAN_NB - 1];
    }
}

__global__ void k_fill(const void* __restrict__ ei, int E, int n) {
    int e = blockIdx.x * blockDim.x + threadIdx.x;
    if (e >= E) return;
    int r = load_idx(ei, e);
    int c = load_idx(ei, (long long)E + e);
    if ((unsigned)r >= (unsigned)n || (unsigned)c >= (unsigned)n) return;
    int pos = atomicAdd(&g_cur[c], 1);
    g_csr[pos] = r;
}

__global__ void k_node_prep(const void* __restrict__ batch, int n) {
    int i = blockIdx.x * blockDim.x + threadIdx.x;
    if (i >= n) return;
    g_dinv[i] = rsqrtf((float)(g_degi[i] + 1));
    int b = load_idx(batch, i);
    if ((unsigned)b >= NGRAPH) b = 0;
    g_batch[i] = b;
    atomicAdd(&g_cnt[b], 1.0f);
}

// ---------------- GEMM: T' = (X @ W) * dinv[row], stored fp16 -----------------
__global__ void k_gemm(const float* __restrict__ X,
                       const float* __restrict__ W,
                       int n, int use_gh) {
    __shared__ float xs[8][C];
    const float* src = use_gh ? (const float*)g_h4 : X;
    int r0 = blockIdx.x * 8;
    int tid = threadIdx.x;
    const float4* src4 = (const float4*)src;
    for (int i = tid; i < 8 * C4; i += 256) {
        int rr = i >> 5, cc = i & 31;
        int r = r0 + rr;
        float4 v = (r < n) ? src4[r * C4 + cc] : make_float4(0.f, 0.f, 0.f, 0.f);
        ((float4*)&xs[rr][0])[cc] = v;
    }
    __syncthreads();
    int lrow = tid >> 5;
    int lane = tid & 31;
    int r = r0 + lrow;
    if (r >= n) return;

    const float4* W4 = (const float4*)W;
    float4 acc = make_float4(0.f, 0.f, 0.f, 0.f);
    for (int k = 0; k < C; k++) {
        float xv = xs[lrow][k];
        float4 w = W4[k * C4 + lane];
        acc.x += xv * w.x; acc.y += xv * w.y;
        acc.z += xv * w.z; acc.w += xv * w.w;
    }
    float di = g_dinv[r];
    __half2 h0 = __float22half2_rn(make_float2(acc.x * di, acc.y * di));
    __half2 h1 = __float22half2_rn(make_float2(acc.z * di, acc.w * di));
    uint2 packed;
    packed.x = *(unsigned int*)&h0;
    packed.y = *(unsigned int*)&h1;
    g_t2h[r * C4 + lane] = packed;
}

// ---------------- CSR gather: h[c] = relu((t'[c] + sum t'[row]) * dinv[c] + b)
__device__ __forceinline__ void acc_half4(float4& acc, uint2 v) {
    float2 f0 = __half22float2(*(__half2*)&v.x);
    float2 f1 = __half22float2(*(__half2*)&v.y);
    acc.x += f0.x; acc.y += f0.y; acc.z += f1.x; acc.w += f1.y;
}

__global__ void k_gather(const float* __restrict__ bias, int n, int pool_mode) {
    int node = blockIdx.x * 8 + (threadIdx.x >> 5);
    int lane = threadIdx.x & 31;
    if (node >= n) return;
    int s = g_off[node], e = g_off[node + 1];

    float4 acc = make_float4(0.f, 0.f, 0.f, 0.f);
    acc_half4(acc, g_t2h[node * C4 + lane]);   // self-loop term
    int i = s;
    for (; i + 4 <= e; i += 4) {
        int r0 = g_csr[i], r1 = g_csr[i + 1], r2 = g_csr[i + 2], r3 = g_csr[i + 3];
        uint2 a = g_t2h[r0 * C4 + lane];
        uint2 b = g_t2h[r1 * C4 + lane];
        uint2 c = g_t2h[r2 * C4 + lane];
        uint2 d = g_t2h[r3 * C4 + lane];
        acc_half4(acc, a); acc_half4(acc, b);
        acc_half4(acc, c); acc_half4(acc, d);
    }
    for (; i < e; i++) acc_half4(acc, g_t2h[g_csr[i] * C4 + lane]);

    float di = g_dinv[node];
    float4 bv = ((const float4*)bias)[lane];
    float4 o;
    o.x = fmaxf(acc.x * di + bv.x, 0.f);
    o.y = fmaxf(acc.y * di + bv.y, 0.f);
    o.z = fmaxf(acc.z * di + bv.z, 0.f);
    o.w = fmaxf(acc.w * di + bv.w, 0.f);

    if (pool_mode) {
        int b = g_batch[node];
        atomicAdd(&g_pool4[b * C4 + lane], o);
    } else {
        g_h4[node * C4 + lane] = o;
    }
}

// ---------------- head: mean -> lin1+relu -> lin2 -> log_softmax -------------
__global__ void k_head(const float* __restrict__ lin1_w,
                       const float* __restrict__ lin1_b,
                       const float* __restrict__ lin2_w,
                       const float* __restrict__ lin2_b,
                       float* __restrict__ out) {
    __shared__ float p[C];
    __shared__ float z1[LIN];
    __shared__ float z2[NCLS];
    int g = blockIdx.x;
    int tid = threadIdx.x;
    float cnt = g_cnt[g];
    if (cnt < 1.f) cnt = 1.f;
    if (tid < C) p[tid] = ((const float*)g_pool4)[g * C + tid] / cnt;
    __syncthreads();

    float acc = lin1_b[tid];
    for (int k = 0; k < C; k++) acc += p[k] * lin1_w[k * LIN + tid];
    z1[tid] = acc > 0.f ? acc : 0.f;
    __syncthreads();

    if (tid < NCLS) {
        float a = lin2_b[tid];
        for (int j = 0; j < LIN; j++) a += z1[j] * lin2_w[j * NCLS + tid];
        z2[tid] = a;
    }
    __syncthreads();

    if (tid == 0) {
        float m = z2[0];
        for (int k = 1; k < NCLS; k++) m = fmaxf(m, z2[k]);
        float s = 0.f;
        for (int k = 0; k < NCLS; k++) s += expf(z2[k] - m);
        float lse = m + logf(s);
        for (int k = 0; k < NCLS; k++) out[g * NCLS + k] = z2[k] - lse;
    }
}

__global__ void k_zero_out(float* out, int n) {
    int i = blockIdx.x * blockDim.x + threadIdx.x;
    if (i < n) out[i] = 0.f;
}

// ---------------- launch ------------------------------------------------------
extern "C" void kernel_launch(void* const* d_in, const int* in_sizes, int n_in,
                              void* d_out, int out_size) {
    const float* x      = (const float*)d_in[0];
    const void*  ei     = d_in[1];
    const void*  batch  = d_in[2];
    const float* W1     = (const float*)d_in[3];
    const float* b1     = (const float*)d_in[4];
    const float* W2     = (const float*)d_in[5];
    const float* b2     = (const float*)d_in[6];
    const float* W3     = (const float*)d_in[7];
    const float* b3     = (const float*)d_in[8];
    const float* lin1_w = (const float*)d_in[9];
    const float* lin1_b = (const float*)d_in[10];
    const float* lin2_w = (const float*)d_in[11];
    const float* lin2_b = (const float*)d_in[12];
    float* out = (float*)d_out;

    const int n = in_sizes[0] / C;          // 50000
    const int E = in_sizes[1] / 2;          // 1600000

    k_detect<<<1, 32>>>((const int*)ei);

    // ---- CSR build + node prep ----
    k_zero_prep<<<(n + 255) / 256, 256>>>(n);
    k_deg_edges<<<(E + 255) / 256, 256>>>(ei, E, n);
    k_scan1<<<SCAN_NB, SCAN_BS>>>(n);
    k_scan2<<<1, 64>>>();
    k_scan3<<<(n + 256) / 256, 256>>>(n);
    k_fill<<<(E + 255) / 256, 256>>>(ei, E, n);
    k_node_prep<<<(n + 255) / 256, 256>>>(batch, n);

    // ---- 3 GCN layers ----
    const int blocks8 = (n + 7) / 8;
    const float* Ws[3] = { W1, W2, W3 };
    const float* bs[3] = { b1, b2, b3 };
    for (int l = 0; l < 3; l++) {
        k_gemm<<<blocks8, 256>>>(x, Ws[l], n, l > 0 ? 1 : 0);
        k_gather<<<blocks8, 256>>>(bs[l], n, l == 2 ? 1 : 0);
    }

    // ---- head ----
    k_zero_out<<<(out_size + 255) / 256, 256>>>(out, out_size);
    k_head<<<NGRAPH, LIN>>>(lin1_w, lin1_b, lin2_w, lin2_b, out);
}

// round 9
// speedup vs baseline: 4.2097x; 2.0247x over previous
#include <cuda_runtime.h>
#include <cuda_fp16.h>
#include <math.h>

#define N_NODES   50000
#define MAX_E     1700000
#define C         128      // IN_C == HID
#define C4        32       // 128 floats = 32 float4
#define CP        136      // padded smem row (halves): 272B, 16B-aligned, conflict-free
#define MB        32       // GEMM rows per block
#define LIN       256
#define NCLS      10
#define NGRAPH    512
#define SCAN_BS   1024
#define SCAN_NB   ((N_NODES + SCAN_BS - 1) / SCAN_BS)   // 49

// ---------------- scratch -----------------------------------------------------
__device__ __half g_x16[N_NODES * C];     // x converted to fp16 (once)
__device__ __half g_h16[N_NODES * C];     // layer activations, fp16
__device__ __half g_t16[N_NODES * C];     // t' = (h @ W) * dinv[row], fp16
__device__ __half g_wt [C * C];           // W^T fp16 (per layer, just-in-time)
__device__ float  g_dinv[N_NODES];
__device__ int    g_degi[N_NODES];
__device__ int    g_off [N_NODES + 1];
__device__ int    g_cur [N_NODES];
__device__ int    g_csr [MAX_E];
__device__ int    g_batch[N_NODES];
__device__ float4 g_pool4[NGRAPH * C4];
__device__ float  g_cnt  [NGRAPH];
__device__ int    g_bsum [SCAN_NB];
__device__ int    g_boff [SCAN_NB];
__device__ int    g_is64;

// ---------------- dtype detection --------------------------------------------
__global__ void k_detect(const int* __restrict__ ei32) {
    if (threadIdx.x == 0 && blockIdx.x == 0) {
        int is64 = 1;
        for (int i = 1; i < 128; i += 2)
            if (ei32[i] != 0) { is64 = 0; break; }
        g_is64 = is64;
    }
}

__device__ __forceinline__ int load_idx(const void* p, long long i) {
    if (g_is64) return (int)((const long long*)p)[i];
    return ((const int*)p)[i];
}

// ---------------- prep --------------------------------------------------------
__global__ void k_zero_prep(int n) {
    int i = blockIdx.x * blockDim.x + threadIdx.x;
    if (i < n) g_degi[i] = 0;
    if (i < NGRAPH * C4) g_pool4[i] = make_float4(0.f, 0.f, 0.f, 0.f);
    if (i < NGRAPH)      g_cnt[i]  = 0.f;
}

__global__ void k_deg_edges(const void* __restrict__ ei, int E, int n) {
    int e = blockIdx.x * blockDim.x + threadIdx.x;
    if (e < E) {
        int c = load_idx(ei, (long long)E + e);
        if ((unsigned)c < (unsigned)n) atomicAdd(&g_degi[c], 1);
    }
}

__global__ void k_scan1(int n) {
    __shared__ int sh[SCAN_BS];
    int i = blockIdx.x * SCAN_BS + threadIdx.x;
    int v = (i < n) ? g_degi[i] : 0;
    sh[threadIdx.x] = v;
    __syncthreads();
    #pragma unroll 1
    for (int off = 1; off < SCAN_BS; off <<= 1) {
        int t = (threadIdx.x >= off) ? sh[threadIdx.x - off] : 0;
        __syncthreads();
        sh[threadIdx.x] += t;
        __syncthreads();
    }
    if (i < n) g_off[i] = sh[threadIdx.x] - v;
    if (threadIdx.x == SCAN_BS - 1) g_bsum[blockIdx.x] = sh[SCAN_BS - 1];
}

__global__ void k_scan2() {
    __shared__ int sh[64];
    int v = (threadIdx.x < SCAN_NB) ? g_bsum[threadIdx.x] : 0;
    sh[threadIdx.x] = v;
    __syncthreads();
    #pragma unroll 1
    for (int off = 1; off < 64; off <<= 1) {
        int t = (threadIdx.x >= off) ? sh[threadIdx.x - off] : 0;
        __syncthreads();
        sh[threadIdx.x] += t;
        __syncthreads();
    }
    if (threadIdx.x < SCAN_NB) g_boff[threadIdx.x] = sh[threadIdx.x] - v;
}

__global__ void k_scan3(int n) {
    int i = blockIdx.x * blockDim.x + threadIdx.x;
    if (i < n) {
        int o = g_off[i] + g_boff[i >> 10];
        g_off[i] = o;
        g_cur[i] = o;
    }
    if (i == n) g_off[n] = g_boff[SCAN_NB - 1] + g_bsum[SCAN_NB - 1];
}

__global__ void k_fill(const void* __restrict__ ei, int E, int n) {
    int e = blockIdx.x * blockDim.x + threadIdx.x;
    if (e >= E) return;
    int r = load_idx(ei, e);
    int c = load_idx(ei, (long long)E + e);
    if ((unsigned)r >= (unsigned)n || (unsigned)c >= (unsigned)n) return;
    int pos = atomicAdd(&g_cur[c], 1);
    g_csr[pos] = r;
}

__global__ void k_node_prep(const void* __restrict__ batch, int n) {
    int i = blockIdx.x * blockDim.x + threadIdx.x;
    if (i >= n) return;
    g_dinv[i] = rsqrtf((float)(g_degi[i] + 1));
    int b = load_idx(batch, i);
    if ((unsigned)b >= NGRAPH) b = 0;
    g_batch[i] = b;
    atomicAdd(&g_cnt[b], 1.0f);
}

// ---------------- conversions -------------------------------------------------
__global__ void k_convert_x(const float* __restrict__ x, int n) {
    int i = blockIdx.x * blockDim.x + threadIdx.x;
    if (i >= n * C4) return;
    float4 v = ((const float4*)x)[i];
    __half2 h0 = __floats2half2_rn(v.x, v.y);
    __half2 h1 = __floats2half2_rn(v.z, v.w);
    uint2 p;
    p.x = *(unsigned*)&h0; p.y = *(unsigned*)&h1;
    ((uint2*)g_x16)[i] = p;
}

__global__ void k_convert_wt(const float* __restrict__ W) {
    int i = blockIdx.x * blockDim.x + threadIdx.x;   // i over C*C
    if (i >= C * C) return;
    int nn = i >> 7, kk = i & 127;
    g_wt[nn * C + kk] = __float2half(W[kk * C + nn]);
}

// ---------------- tensor-core GEMM: T' = (H @ W) * dinv[row], fp16 ------------
// mma.sync.m16n8k16 f32.f16.f16.f32; A row-major from xs, B col-major from
// W^T rows (ws[n][k]). Block: 256 thr (8 warps), MB=32 rows, full N=K=128.
__global__ void k_gemm_mma(int n, int use_h) {
    __shared__ __half xs[MB][CP];
    __shared__ __half ws[C][CP];
    const __half* src = use_h ? g_h16 : g_x16;
    int tid = threadIdx.x;
    int m0 = blockIdx.x * MB;

    // stage W^T: 128 rows x 16 uint4
    for (int i = tid; i < C * (C / 8); i += 256) {
        int r = i >> 4, c8 = (i & 15) << 3;
        *(uint4*)&ws[r][c8] = *(const uint4*)&g_wt[r * C + c8];
    }
    // stage x tile: 32 rows x 16 uint4, zero-fill OOB
    for (int i = tid; i < MB * (C / 8); i += 256) {
        int r = i >> 4, c8 = (i & 15) << 3;
        int gr = m0 + r;
        uint4 v = make_uint4(0, 0, 0, 0);
        if (gr < n) v = *(const uint4*)&src[(long long)gr * C + c8];
        *(uint4*)&xs[r][c8] = v;
    }
    __syncthreads();

    int w = tid >> 5, l = tid & 31;
    int q = l >> 2, t = l & 3;
    int mt = (w & 1) << 4;        // 0 or 16
    int nq = (w >> 1) << 5;       // 0,32,64,96

    float acc[4][4];
    #pragma unroll
    for (int j = 0; j < 4; j++)
        #pragma unroll
        for (int k = 0; k < 4; k++) acc[j][k] = 0.f;

    #pragma unroll
    for (int ks = 0; ks < C; ks += 16) {
        unsigned a0 = *(unsigned*)&xs[mt + q][ks + t * 2];
        unsigned a1 = *(unsigned*)&xs[mt + q + 8][ks + t * 2];
        unsigned a2 = *(unsigned*)&xs[mt + q][ks + t * 2 + 8];
        unsigned a3 = *(unsigned*)&xs[mt + q + 8][ks + t * 2 + 8];
        #pragma unroll
        for (int j = 0; j < 4; j++) {
            unsigned b0 = *(unsigned*)&ws[nq + j * 8 + q][ks + t * 2];
            unsigned b1 = *(unsigned*)&ws[nq + j * 8 + q][ks + t * 2 + 8];
            asm volatile(
                "mma.sync.aligned.m16n8k16.row.col.f32.f16.f16.f32 "
                "{%0,%1,%2,%3}, {%4,%5,%6,%7}, {%8,%9}, {%0,%1,%2,%3};"
                : "+f"(acc[j][0]), "+f"(acc[j][1]), "+f"(acc[j][2]), "+f"(acc[j][3])
                : "r"(a0), "r"(a1), "r"(a2), "r"(a3), "r"(b0), "r"(b1));
        }
    }

    // epilogue: scale by dinv[row], store fp16 half2 pairs
    int r0 = m0 + mt + q;
    int r1 = r0 + 8;
    float d0 = (r0 < n) ? g_dinv[r0] : 0.f;
    float d1 = (r1 < n) ? g_dinv[r1] : 0.f;
    #pragma unroll
    for (int j = 0; j < 4; j++) {
        int col = nq + j * 8 + t * 2;
        if (r0 < n) {
            __half2 h = __floats2half2_rn(acc[j][0] * d0, acc[j][1] * d0);
            *(__half2*)&g_t16[(long long)r0 * C + col] = h;
        }
        if (r1 < n) {
            __half2 h = __floats2half2_rn(acc[j][2] * d1, acc[j][3] * d1);
            *(__half2*)&g_t16[(long long)r1 * C + col] = h;
        }
    }
}

// ---------------- CSR gather: h[c] = relu((t'[c] + sum t'[row]) * dinv[c] + b)
__device__ __forceinline__ void acc_half4(float4& acc, uint2 v) {
    float2 f0 = __half22float2(*(__half2*)&v.x);
    float2 f1 = __half22float2(*(__half2*)&v.y);
    acc.x += f0.x; acc.y += f0.y; acc.z += f1.x; acc.w += f1.y;
}

__global__ void k_gather(const float* __restrict__ bias, int n, int pool_mode) {
    int node = blockIdx.x * 8 + (threadIdx.x >> 5);
    int lane = threadIdx.x & 31;
    if (node >= n) return;
    int s = g_off[node], e = g_off[node + 1];

    const uint2* T2 = (const uint2*)g_t16;
    float4 acc = make_float4(0.f, 0.f, 0.f, 0.f);
    acc_half4(acc, T2[node * C4 + lane]);   // self-loop term
    int i = s;
    for (; i + 4 <= e; i += 4) {
        int r0 = g_csr[i], r1 = g_csr[i + 1], r2 = g_csr[i + 2], r3 = g_csr[i + 3];
        uint2 a = T2[r0 * C4 + lane];
        uint2 b = T2[r1 * C4 + lane];
        uint2 c = T2[r2 * C4 + lane];
        uint2 d = T2[r3 * C4 + lane];
        acc_half4(acc, a); acc_half4(acc, b);
        acc_half4(acc, c); acc_half4(acc, d);
    }
    for (; i < e; i++) acc_half4(acc, T2[g_csr[i] * C4 + lane]);

    float di = g_dinv[node];
    float4 bv = ((const float4*)bias)[lane];
    float4 o;
    o.x = fmaxf(acc.x * di + bv.x, 0.f);
    o.y = fmaxf(acc.y * di + bv.y, 0.f);
    o.z = fmaxf(acc.z * di + bv.z, 0.f);
    o.w = fmaxf(acc.w * di + bv.w, 0.f);

    if (pool_mode) {
        int b = g_batch[node];
        atomicAdd(&g_pool4[b * C4 + lane], o);
    } else {
        __half2 h0 = __floats2half2_rn(o.x, o.y);
        __half2 h1 = __floats2half2_rn(o.z, o.w);
        uint2 p;
        p.x = *(unsigned*)&h0; p.y = *(unsigned*)&h1;
        ((uint2*)g_h16)[node * C4 + lane] = p;
    }
}

// ---------------- head: mean -> lin1+relu -> lin2 -> log_softmax -------------
__global__ void k_head(const float* __restrict__ lin1_w,
                       const float* __restrict__ lin1_b,
                       const float* __restrict__ lin2_w,
                       const float* __restrict__ lin2_b,
                       float* __restrict__ out) {
    __shared__ float p[C];
    __shared__ float z1[LIN];
    __shared__ float z2[NCLS];
    int g = blockIdx.x;
    int tid = threadIdx.x;
    float cnt = g_cnt[g];
    if (cnt < 1.f) cnt = 1.f;
    if (tid < C) p[tid] = ((const float*)g_pool4)[g * C + tid] / cnt;
    __syncthreads();

    float acc = lin1_b[tid];
    for (int k = 0; k < C; k++) acc += p[k] * lin1_w[k * LIN + tid];
    z1[tid] = acc > 0.f ? acc : 0.f;
    __syncthreads();

    if (tid < NCLS) {
        float a = lin2_b[tid];
        for (int j = 0; j < LIN; j++) a += z1[j] * lin2_w[j * NCLS + tid];
        z2[tid] = a;
    }
    __syncthreads();

    if (tid == 0) {
        float m = z2[0];
        for (int k = 1; k < NCLS; k++) m = fmaxf(m, z2[k]);
        float s = 0.f;
        for (int k = 0; k < NCLS; k++) s += expf(z2[k] - m);
        float lse = m + logf(s);
        for (int k = 0; k < NCLS; k++) out[g * NCLS + k] = z2[k] - lse;
    }
}

__global__ void k_zero_out(float* out, int n) {
    int i = blockIdx.x * blockDim.x + threadIdx.x;
    if (i < n) out[i] = 0.f;
}

// ---------------- launch ------------------------------------------------------
extern "C" void kernel_launch(void* const* d_in, const int* in_sizes, int n_in,
                              void* d_out, int out_size) {
    const float* x      = (const float*)d_in[0];
    const void*  ei     = d_in[1];
    const void*  batch  = d_in[2];
    const float* W1     = (const float*)d_in[3];
    const float* b1     = (const float*)d_in[4];
    const float* W2     = (const float*)d_in[5];
    const float* b2     = (const float*)d_in[6];
    const float* W3     = (const float*)d_in[7];
    const float* b3     = (const float*)d_in[8];
    const float* lin1_w = (const float*)d_in[9];
    const float* lin1_b = (const float*)d_in[10];
    const float* lin2_w = (const float*)d_in[11];
    const float* lin2_b = (const float*)d_in[12];
    float* out = (float*)d_out;

    const int n = in_sizes[0] / C;          // 50000
    const int E = in_sizes[1] / 2;          // 1600000

    k_detect<<<1, 32>>>((const int*)ei);

    // ---- CSR build + node prep ----
    k_zero_prep<<<(n + 255) / 256, 256>>>(n);
    k_deg_edges<<<(E + 255) / 256, 256>>>(ei, E, n);
    k_scan1<<<SCAN_NB, SCAN_BS>>>(n);
    k_scan2<<<1, 64>>>();
    k_scan3<<<(n + 256) / 256, 256>>>(n);
    k_fill<<<(E + 255) / 256, 256>>>(ei, E, n);
    k_node_prep<<<(n + 255) / 256, 256>>>(batch, n);

    // ---- fp16 input conversion ----
    k_convert_x<<<(n * C4 + 255) / 256, 256>>>(x, n);

    // ---- 3 GCN layers ----
    const int mma_blocks  = (n + MB - 1) / MB;
    const int gath_blocks = (n + 7) / 8;
    const float* Ws[3] = { W1, W2, W3 };
    const float* bs[3] = { b1, b2, b3 };
    for (int l = 0; l < 3; l++) {
        k_convert_wt<<<(C * C + 255) / 256, 256>>>(Ws[l]);
        k_gemm_mma<<<mma_blocks, 256>>>(n, l > 0 ? 1 : 0);
        k_gather<<<gath_blocks, 256>>>(bs[l], n, l == 2 ? 1 : 0);
    }

    // ---- head ----
    k_zero_out<<<(out_size + 255) / 256, 256>>>(out, out_size);
    k_head<<<NGRAPH, LIN>>>(lin1_w, lin1_b, lin2_w, lin2_b, out);
}

// round 10
// speedup vs baseline: 4.2457x; 1.0085x over previous
#include <cuda_runtime.h>
#include <cuda_fp16.h>
#include <math.h>

#define N_NODES   50000
#define MAX_E     1700000
#define C         128      // IN_C == HID
#define C4        32       // 128 floats = 32 float4
#define CP        136      // padded smem row (halves)
#define MB        32       // GEMM rows per block
#define LIN       256
#define NCLS      10
#define NGRAPH    512
#define SCAN_BS   1024
#define SCAN_NB   ((N_NODES + SCAN_BS - 1) / SCAN_BS)   // 49

// ---------------- scratch -----------------------------------------------------
__device__ __half        g_x16[N_NODES * C];   // x in fp16 (once)
__device__ __half        g_h16[N_NODES * C];   // activations, fp16
__device__ unsigned int  g_t8 [N_NODES * C4];  // t' in e4m3: 4 channels per uint
__device__ __half        g_wt [C * C];         // W^T fp16 (per layer)
__device__ float  g_dinv[N_NODES];
__device__ int    g_degi[N_NODES];
__device__ int    g_off [N_NODES + 1];
__device__ int    g_cur [N_NODES];
__device__ int    g_csr [MAX_E];
__device__ int    g_batch[N_NODES];
__device__ float4 g_pool4[NGRAPH * C4];
__device__ float  g_cnt  [NGRAPH];
__device__ int    g_bsum [SCAN_NB];
__device__ int    g_boff [SCAN_NB];
__device__ int    g_is64;

// ---------------- dtype detection --------------------------------------------
__global__ void k_detect(const int* __restrict__ ei32) {
    if (threadIdx.x == 0 && blockIdx.x == 0) {
        int is64 = 1;
        for (int i = 1; i < 128; i += 2)
            if (ei32[i] != 0) { is64 = 0; break; }
        g_is64 = is64;
    }
}

__device__ __forceinline__ int load_idx(const void* p, long long i) {
    if (g_is64) return (int)((const long long*)p)[i];
    return ((const int*)p)[i];
}

// ---------------- prep --------------------------------------------------------
__global__ void k_zero_prep(int n) {
    int i = blockIdx.x * blockDim.x + threadIdx.x;
    if (i < n) g_degi[i] = 0;
    if (i < NGRAPH * C4) g_pool4[i] = make_float4(0.f, 0.f, 0.f, 0.f);
    if (i < NGRAPH)      g_cnt[i]  = 0.f;
}

__global__ void k_deg_edges(const void* __restrict__ ei, int E, int n) {
    int e = blockIdx.x * blockDim.x + threadIdx.x;
    if (e < E) {
        int c = load_idx(ei, (long long)E + e);
        if ((unsigned)c < (unsigned)n) atomicAdd(&g_degi[c], 1);
    }
}

__global__ void k_scan1(int n) {
    __shared__ int sh[SCAN_BS];
    int i = blockIdx.x * SCAN_BS + threadIdx.x;
    int v = (i < n) ? g_degi[i] : 0;
    sh[threadIdx.x] = v;
    __syncthreads();
    #pragma unroll 1
    for (int off = 1; off < SCAN_BS; off <<= 1) {
        int t = (threadIdx.x >= off) ? sh[threadIdx.x - off] : 0;
        __syncthreads();
        sh[threadIdx.x] += t;
        __syncthreads();
    }
    if (i < n) g_off[i] = sh[threadIdx.x] - v;
    if (threadIdx.x == SCAN_BS - 1) g_bsum[blockIdx.x] = sh[SCAN_BS - 1];
}

__global__ void k_scan2() {
    __shared__ int sh[64];
    int v = (threadIdx.x < SCAN_NB) ? g_bsum[threadIdx.x] : 0;
    sh[threadIdx.x] = v;
    __syncthreads();
    #pragma unroll 1
    for (int off = 1; off < 64; off <<= 1) {
        int t = (threadIdx.x >= off) ? sh[threadIdx.x - off] : 0;
        __syncthreads();
        sh[threadIdx.x] += t;
        __syncthreads();
    }
    if (threadIdx.x < SCAN_NB) g_boff[threadIdx.x] = sh[threadIdx.x] - v;
}

__global__ void k_scan3(int n) {
    int i = blockIdx.x * blockDim.x + threadIdx.x;
    if (i < n) {
        int o = g_off[i] + g_boff[i >> 10];
        g_off[i] = o;
        g_cur[i] = o;
    }
    if (i == n) g_off[n] = g_boff[SCAN_NB - 1] + g_bsum[SCAN_NB - 1];
}

__global__ void k_fill(const void* __restrict__ ei, int E, int n) {
    int e = blockIdx.x * blockDim.x + threadIdx.x;
    if (e >= E) return;
    int r = load_idx(ei, e);
    int c = load_idx(ei, (long long)E + e);
    if ((unsigned)r >= (unsigned)n || (unsigned)c >= (unsigned)n) return;
    int pos = atomicAdd(&g_cur[c], 1);
    g_csr[pos] = r;
}

__global__ void k_node_prep(const void* __restrict__ batch, int n) {
    int i = blockIdx.x * blockDim.x + threadIdx.x;
    if (i >= n) return;
    g_dinv[i] = rsqrtf((float)(g_degi[i] + 1));
    int b = load_idx(batch, i);
    if ((unsigned)b >= NGRAPH) b = 0;
    g_batch[i] = b;
    atomicAdd(&g_cnt[b], 1.0f);
}

// ---------------- conversions -------------------------------------------------
__global__ void k_convert_x(const float* __restrict__ x, int n) {
    int i = blockIdx.x * blockDim.x + threadIdx.x;
    if (i >= n * C4) return;
    float4 v = ((const float4*)x)[i];
    __half2 h0 = __floats2half2_rn(v.x, v.y);
    __half2 h1 = __floats2half2_rn(v.z, v.w);
    uint2 p;
    p.x = *(unsigned*)&h0; p.y = *(unsigned*)&h1;
    ((uint2*)g_x16)[i] = p;
}

__global__ void k_convert_wt(const float* __restrict__ W) {
    int i = blockIdx.x * blockDim.x + threadIdx.x;   // i over C*C
    if (i >= C * C) return;
    int nn = i >> 7, kk = i & 127;
    g_wt[nn * C + kk] = __float2half(W[kk * C + nn]);
}

// ---------------- fp8 helpers -------------------------------------------------
__device__ __forceinline__ unsigned short f2_to_e4m3x2(float lo, float hi) {
    unsigned short u;
    asm("cvt.rn.satfinite.e4m3x2.f32 %0, %1, %2;" : "=h"(u) : "f"(hi), "f"(lo));
    return u;
}

__device__ __forceinline__ void acc_fp8x4(float4& acc, unsigned v) {
    unsigned short lo = (unsigned short)(v & 0xffffu);
    unsigned short hi = (unsigned short)(v >> 16);
    unsigned h0, h1;
    asm("cvt.rn.f16x2.e4m3x2 %0, %1;" : "=r"(h0) : "h"(lo));
    asm("cvt.rn.f16x2.e4m3x2 %0, %1;" : "=r"(h1) : "h"(hi));
    float2 f0 = __half22float2(*(__half2*)&h0);
    float2 f1 = __half22float2(*(__half2*)&h1);
    acc.x += f0.x; acc.y += f0.y; acc.z += f1.x; acc.w += f1.y;
}

// ---------------- tensor-core GEMM: T' = (H @ W) * dinv[row] -> e4m3 ----------
__global__ void k_gemm_mma(int n, int use_h) {
    __shared__ __half xs[MB][CP];
    __shared__ __half ws[C][CP];
    const __half* src = use_h ? g_h16 : g_x16;
    int tid = threadIdx.x;
    int m0 = blockIdx.x * MB;

    for (int i = tid; i < C * (C / 8); i += 256) {
        int r = i >> 4, c8 = (i & 15) << 3;
        *(uint4*)&ws[r][c8] = *(const uint4*)&g_wt[r * C + c8];
    }
    for (int i = tid; i < MB * (C / 8); i += 256) {
        int r = i >> 4, c8 = (i & 15) << 3;
        int gr = m0 + r;
        uint4 v = make_uint4(0, 0, 0, 0);
        if (gr < n) v = *(const uint4*)&src[(long long)gr * C + c8];
        *(uint4*)&xs[r][c8] = v;
    }
    __syncthreads();

    int w = tid >> 5, l = tid & 31;
    int q = l >> 2, t = l & 3;
    int mt = (w & 1) << 4;        // 0 or 16
    int nq = (w >> 1) << 5;       // 0,32,64,96

    float acc[4][4];
    #pragma unroll
    for (int j = 0; j < 4; j++)
        #pragma unroll
        for (int k = 0; k < 4; k++) acc[j][k] = 0.f;

    #pragma unroll
    for (int ks = 0; ks < C; ks += 16) {
        unsigned a0 = *(unsigned*)&xs[mt + q][ks + t * 2];
        unsigned a1 = *(unsigned*)&xs[mt + q + 8][ks + t * 2];
        unsigned a2 = *(unsigned*)&xs[mt + q][ks + t * 2 + 8];
        unsigned a3 = *(unsigned*)&xs[mt + q + 8][ks + t * 2 + 8];
        #pragma unroll
        for (int j = 0; j < 4; j++) {
            unsigned b0 = *(unsigned*)&ws[nq + j * 8 + q][ks + t * 2];
            unsigned b1 = *(unsigned*)&ws[nq + j * 8 + q][ks + t * 2 + 8];
            asm volatile(
                "mma.sync.aligned.m16n8k16.row.col.f32.f16.f16.f32 "
                "{%0,%1,%2,%3}, {%4,%5,%6,%7}, {%8,%9}, {%0,%1,%2,%3};"
                : "+f"(acc[j][0]), "+f"(acc[j][1]), "+f"(acc[j][2]), "+f"(acc[j][3])
                : "r"(a0), "r"(a1), "r"(a2), "r"(a3), "r"(b0), "r"(b1));
        }
    }

    // epilogue: scale by dinv[row], convert to e4m3 pairs (ushort per 2 chans)
    int r0 = m0 + mt + q;
    int r1 = r0 + 8;
    float d0 = (r0 < n) ? g_dinv[r0] : 0.f;
    float d1 = (r1 < n) ? g_dinv[r1] : 0.f;
    unsigned char* T8 = (unsigned char*)g_t8;
    #pragma unroll
    for (int j = 0; j < 4; j++) {
        int col = nq + j * 8 + t * 2;
        if (r0 < n) {
            unsigned short u = f2_to_e4m3x2(acc[j][0] * d0, acc[j][1] * d0);
            *(unsigned short*)&T8[(long long)r0 * C + col] = u;
        }
        if (r1 < n) {
            unsigned short u = f2_to_e4m3x2(acc[j][2] * d1, acc[j][3] * d1);
            *(unsigned short*)&T8[(long long)r1 * C + col] = u;
        }
    }
}

// ---------------- CSR gather (fp8 messages, fp32 accum) -----------------------
__global__ void k_gather(const float* __restrict__ bias, int n, int pool_mode) {
    int node = blockIdx.x * 8 + (threadIdx.x >> 5);
    int lane = threadIdx.x & 31;
    if (node >= n) return;
    int s = g_off[node], e = g_off[node + 1];

    const unsigned* T8 = g_t8;
    float4 acc = make_float4(0.f, 0.f, 0.f, 0.f);
    acc_fp8x4(acc, T8[node * C4 + lane]);   // self-loop term
    int i = s;
    for (; i + 8 <= e; i += 8) {
        unsigned v0 = T8[g_csr[i]     * C4 + lane];
        unsigned v1 = T8[g_csr[i + 1] * C4 + lane];
        unsigned v2 = T8[g_csr[i + 2] * C4 + lane];
        unsigned v3 = T8[g_csr[i + 3] * C4 + lane];
        unsigned v4 = T8[g_csr[i + 4] * C4 + lane];
        unsigned v5 = T8[g_csr[i + 5] * C4 + lane];
        unsigned v6 = T8[g_csr[i + 6] * C4 + lane];
        unsigned v7 = T8[g_csr[i + 7] * C4 + lane];
        acc_fp8x4(acc, v0); acc_fp8x4(acc, v1);
        acc_fp8x4(acc, v2); acc_fp8x4(acc, v3);
        acc_fp8x4(acc, v4); acc_fp8x4(acc, v5);
        acc_fp8x4(acc, v6); acc_fp8x4(acc, v7);
    }
    for (; i < e; i++) acc_fp8x4(acc, T8[g_csr[i] * C4 + lane]);

    float di = g_dinv[node];
    float4 bv = ((const float4*)bias)[lane];
    float4 o;
    o.x = fmaxf(acc.x * di + bv.x, 0.f);
    o.y = fmaxf(acc.y * di + bv.y, 0.f);
    o.z = fmaxf(acc.z * di + bv.z, 0.f);
    o.w = fmaxf(acc.w * di + bv.w, 0.f);

    if (pool_mode) {
        int b = g_batch[node];
        atomicAdd(&g_pool4[b * C4 + lane], o);
    } else {
        __half2 h0 = __floats2half2_rn(o.x, o.y);
        __half2 h1 = __floats2half2_rn(o.z, o.w);
        uint2 p;
        p.x = *(unsigned*)&h0; p.y = *(unsigned*)&h1;
        ((uint2*)g_h16)[node * C4 + lane] = p;
    }
}

// ---------------- head: mean -> lin1+relu -> lin2 -> log_softmax -------------
__global__ void k_head(const float* __restrict__ lin1_w,
                       const float* __restrict__ lin1_b,
                       const float* __restrict__ lin2_w,
                       const float* __restrict__ lin2_b,
                       float* __restrict__ out) {
    __shared__ float p[C];
    __shared__ float z1[LIN];
    __shared__ float z2[NCLS];
    int g = blockIdx.x;
    int tid = threadIdx.x;
    float cnt = g_cnt[g];
    if (cnt < 1.f) cnt = 1.f;
    if (tid < C) p[tid] = ((const float*)g_pool4)[g * C + tid] / cnt;
    __syncthreads();

    float acc = lin1_b[tid];
    for (int k = 0; k < C; k++) acc += p[k] * lin1_w[k * LIN + tid];
    z1[tid] = acc > 0.f ? acc : 0.f;
    __syncthreads();

    if (tid < NCLS) {
        float a = lin2_b[tid];
        for (int j = 0; j < LIN; j++) a += z1[j] * lin2_w[j * NCLS + tid];
        z2[tid] = a;
    }
    __syncthreads();

    if (tid == 0) {
        float m = z2[0];
        for (int k = 1; k < NCLS; k++) m = fmaxf(m, z2[k]);
        float s = 0.f;
        for (int k = 0; k < NCLS; k++) s += expf(z2[k] - m);
        float lse = m + logf(s);
        for (int k = 0; k < NCLS; k++) out[g * NCLS + k] = z2[k] - lse;
    }
}

__global__ void k_zero_out(float* out, int n) {
    int i = blockIdx.x * blockDim.x + threadIdx.x;
    if (i < n) out[i] = 0.f;
}

// ---------------- launch ------------------------------------------------------
extern "C" void kernel_launch(void* const* d_in, const int* in_sizes, int n_in,
                              void* d_out, int out_size) {
    const float* x      = (const float*)d_in[0];
    const void*  ei     = d_in[1];
    const void*  batch  = d_in[2];
    const float* W1     = (const float*)d_in[3];
    const float* b1     = (const float*)d_in[4];
    const float* W2     = (const float*)d_in[5];
    const float* b2     = (const float*)d_in[6];
    const float* W3     = (const float*)d_in[7];
    const float* b3     = (const float*)d_in[8];
    const float* lin1_w = (const float*)d_in[9];
    const float* lin1_b = (const float*)d_in[10];
    const float* lin2_w = (const float*)d_in[11];
    const float* lin2_b = (const float*)d_in[12];
    float* out = (float*)d_out;

    const int n = in_sizes[0] / C;          // 50000
    const int E = in_sizes[1] / 2;          // 1600000

    k_detect<<<1, 32>>>((const int*)ei);

    // ---- CSR build + node prep ----
    k_zero_prep<<<(n + 255) / 256, 256>>>(n);
    k_deg_edges<<<(E + 255) / 256, 256>>>(ei, E, n);
    k_scan1<<<SCAN_NB, SCAN_BS>>>(n);
    k_scan2<<<1, 64>>>();
    k_scan3<<<(n + 256) / 256, 256>>>(n);
    k_fill<<<(E + 255) / 256, 256>>>(ei, E, n);
    k_node_prep<<<(n + 255) / 256, 256>>>(batch, n);

    // ---- fp16 input conversion ----
    k_convert_x<<<(n * C4 + 255) / 256, 256>>>(x, n);

    // ---- 3 GCN layers ----
    const int mma_blocks  = (n + MB - 1) / MB;
    const int gath_blocks = (n + 7) / 8;
    const float* Ws[3] = { W1, W2, W3 };
    const float* bs[3] = { b1, b2, b3 };
    for (int l = 0; l < 3; l++) {
        k_convert_wt<<<(C * C + 255) / 256, 256>>>(Ws[l]);
        k_gemm_mma<<<mma_blocks, 256>>>(n, l > 0 ? 1 : 0);
        k_gather<<<gath_blocks, 256>>>(bs[l], n, l == 2 ? 1 : 0);
    }

    // ---- head ----
    k_zero_out<<<(out_size + 255) / 256, 256>>>(out, out_size);
    k_head<<<NGRAPH, LIN>>>(lin1_w, lin1_b, lin2_w, lin2_b, out);
}

// round 12
// speedup vs baseline: 4.4711x; 1.0531x over previous
#include <cuda_runtime.h>
#include <cuda_fp16.h>
#include <math.h>

#define N_NODES   50000
#define MAX_E     1700000
#define C         128
#define C4        32
#define CP        136
#define MB        32
#define LIN       256
#define NCLS      10
#define NGRAPH    512
#define SCAN_BS   1024
#define SCAN_NB   ((N_NODES + SCAN_BS - 1) / SCAN_BS)   // 49

// ---------------- scratch -----------------------------------------------------
__device__ __half        g_h16[N_NODES * C];   // activations, fp16
__device__ unsigned int  g_t8 [N_NODES * C4];  // t' in e4m3: 4 chans per uint
__device__ __half        g_wt [3 * C * C];     // W^T fp16, all 3 layers
__device__ float  g_dinv[N_NODES];
__device__ int    g_degi[N_NODES];
__device__ int    g_off [N_NODES + 1];
__device__ int    g_cur [N_NODES];
__device__ int    g_csr [MAX_E];
__device__ int    g_row32[MAX_E];
__device__ int    g_col32[MAX_E];
__device__ int    g_batch[N_NODES];
__device__ float4 g_pool4[NGRAPH * C4];
__device__ float  g_cnt  [NGRAPH];
__device__ int    g_bsum [SCAN_NB];
__device__ int    g_boff [SCAN_NB];
__device__ int    g_is64;

// ---------------- init: dtype detect + zero everything ------------------------
__global__ void k_init(const int* __restrict__ ei32, int n) {
    int i = blockIdx.x * blockDim.x + threadIdx.x;
    if (i == 0) {
        int is64 = 1;
        for (int k = 1; k < 128; k += 2)
            if (ei32[k] != 0) { is64 = 0; break; }
        g_is64 = is64;
    }
    if (i < n) g_degi[i] = 0;
    if (i < NGRAPH * C4) g_pool4[i] = make_float4(0.f, 0.f, 0.f, 0.f);
    if (i < NGRAPH)      g_cnt[i]  = 0.f;
}

__device__ __forceinline__ int load_idx(const void* p, long long i) {
    if (g_is64) return (int)((const long long*)p)[i];
    return ((const int*)p)[i];
}

// ---------------- edge prep: one pass over int64 ei ---------------------------
__global__ void k_edge_prep(const void* __restrict__ ei, int E, int n) {
    int e = blockIdx.x * blockDim.x + threadIdx.x;
    if (e >= E) return;
    int r = load_idx(ei, e);
    int c = load_idx(ei, (long long)E + e);
    g_row32[e] = r;
    g_col32[e] = c;
    if ((unsigned)c < (unsigned)n) atomicAdd(&g_degi[c], 1);
}

// ---- 3-phase scan ------------------------------------------------------------
__global__ void k_scan1(int n) {
    __shared__ int sh[SCAN_BS];
    int i = blockIdx.x * SCAN_BS + threadIdx.x;
    int v = (i < n) ? g_degi[i] : 0;
    sh[threadIdx.x] = v;
    __syncthreads();
    #pragma unroll 1
    for (int off = 1; off < SCAN_BS; off <<= 1) {
        int t = (threadIdx.x >= off) ? sh[threadIdx.x - off] : 0;
        __syncthreads();
        sh[threadIdx.x] += t;
        __syncthreads();
    }
    if (i < n) g_off[i] = sh[threadIdx.x] - v;
    if (threadIdx.x == SCAN_BS - 1) g_bsum[blockIdx.x] = sh[SCAN_BS - 1];
}

__global__ void k_scan2() {
    __shared__ int sh[64];
    int v = (threadIdx.x < SCAN_NB) ? g_bsum[threadIdx.x] : 0;
    sh[threadIdx.x] = v;
    __syncthreads();
    #pragma unroll 1
    for (int off = 1; off < 64; off <<= 1) {
        int t = (threadIdx.x >= off) ? sh[threadIdx.x - off] : 0;
        __syncthreads();
        sh[threadIdx.x] += t;
        __syncthreads();
    }
    if (threadIdx.x < SCAN_NB) g_boff[threadIdx.x] = sh[threadIdx.x] - v;
}

__global__ void k_scan3(int n) {
    int i = blockIdx.x * blockDim.x + threadIdx.x;
    if (i < n) {
        int o = g_off[i] + g_boff[i >> 10];
        g_off[i] = o;
        g_cur[i] = o;
    }
    if (i == n) g_off[n] = g_boff[SCAN_NB - 1] + g_bsum[SCAN_NB - 1];
}

__global__ void k_fill(int E, int n) {
    int e = blockIdx.x * blockDim.x + threadIdx.x;
    if (e >= E) return;
    int r = g_row32[e];
    int c = g_col32[e];
    if ((unsigned)r >= (unsigned)n || (unsigned)c >= (unsigned)n) return;
    int pos = atomicAdd(&g_cur[c], 1);
    g_csr[pos] = r;
}

__global__ void k_node_prep(const void* __restrict__ batch, int n) {
    int i = blockIdx.x * blockDim.x + threadIdx.x;
    if (i >= n) return;
    g_dinv[i] = rsqrtf((float)(g_degi[i] + 1));
    int b = load_idx(batch, i);
    if ((unsigned)b >= NGRAPH) b = 0;
    g_batch[i] = b;
    atomicAdd(&g_cnt[b], 1.0f);
}

// ---------------- all-3 weight transpose to fp16 ------------------------------
__global__ void k_wt_all(const float* __restrict__ W1,
                         const float* __restrict__ W2,
                         const float* __restrict__ W3) {
    int i = blockIdx.x * blockDim.x + threadIdx.x;   // over 3*C*C
    if (i >= 3 * C * C) return;
    int l = i / (C * C);
    int j = i - l * (C * C);
    int nn = j >> 7, kk = j & 127;
    const float* W = (l == 0) ? W1 : (l == 1) ? W2 : W3;
    g_wt[i] = __float2half(W[kk * C + nn]);   // g_wt[l][nn][kk]
}

// ---------------- fp8 helpers -------------------------------------------------
__device__ __forceinline__ unsigned short f2_to_e4m3x2(float lo, float hi) {
    unsigned short u;
    asm("cvt.rn.satfinite.e4m3x2.f32 %0, %1, %2;" : "=h"(u) : "f"(hi), "f"(lo));
    return u;
}

__device__ __forceinline__ void acc_fp8x4(float4& acc, unsigned v) {
    unsigned short lo = (unsigned short)(v & 0xffffu);
    unsigned short hi = (unsigned short)(v >> 16);
    unsigned h0, h1;
    asm("cvt.rn.f16x2.e4m3x2 %0, %1;" : "=r"(h0) : "h"(lo));
    asm("cvt.rn.f16x2.e4m3x2 %0, %1;" : "=r"(h1) : "h"(hi));
    float2 f0 = __half22float2(*(__half2*)&h0);
    float2 f1 = __half22float2(*(__half2*)&h1);
    acc.x += f0.x; acc.y += f0.y; acc.z += f1.x; acc.w += f1.y;
}

// ---------------- tensor-core GEMM: T' = (H @ W) * dinv[row] -> e4m3 ----------
// layer 0 stages fp32 x (converting inline); layers 1-2 stage fp16 g_h16.
__global__ void k_gemm_mma(const float* __restrict__ xf, int n, int layer) {
    __shared__ __half xs[MB][CP];
    __shared__ __half ws[C][CP];
    int tid = threadIdx.x;
    int m0 = blockIdx.x * MB;
    const __half* wt = g_wt + layer * C * C;

    for (int i = tid; i < C * (C / 8); i += 256) {
        int r = i >> 4, c8 = (i & 15) << 3;
        *(uint4*)&ws[r][c8] = *(const uint4*)&wt[r * C + c8];
    }
    if (layer == 0) {
        for (int i = tid; i < MB * (C / 8); i += 256) {
            int r = i >> 4, c8 = (i & 15) << 3;
            int gr = m0 + r;
            __half2 h0 = __floats2half2_rn(0.f, 0.f), h1 = h0, h2 = h0, h3 = h0;
            if (gr < n) {
                const float4* p = (const float4*)&xf[(long long)gr * C + c8];
                float4 a = p[0], b = p[1];
                h0 = __floats2half2_rn(a.x, a.y);
                h1 = __floats2half2_rn(a.z, a.w);
                h2 = __floats2half2_rn(b.x, b.y);
                h3 = __floats2half2_rn(b.z, b.w);
            }
            uint4 v;
            v.x = *(unsigned*)&h0; v.y = *(unsigned*)&h1;
            v.z = *(unsigned*)&h2; v.w = *(unsigned*)&h3;
            *(uint4*)&xs[r][c8] = v;
        }
    } else {
        for (int i = tid; i < MB * (C / 8); i += 256) {
            int r = i >> 4, c8 = (i & 15) << 3;
            int gr = m0 + r;
            uint4 v = make_uint4(0, 0, 0, 0);
            if (gr < n) v = *(const uint4*)&g_h16[(long long)gr * C + c8];
            *(uint4*)&xs[r][c8] = v;
        }
    }
    __syncthreads();

    int w = tid >> 5, l = tid & 31;
    int q = l >> 2, t = l & 3;
    int mt = (w & 1) << 4;
    int nq = (w >> 1) << 5;

    float acc[4][4];
    #pragma unroll
    for (int j = 0; j < 4; j++)
        #pragma unroll
        for (int k = 0; k < 4; k++) acc[j][k] = 0.f;

    #pragma unroll
    for (int ks = 0; ks < C; ks += 16) {
        unsigned a0 = *(unsigned*)&xs[mt + q][ks + t * 2];
        unsigned a1 = *(unsigned*)&xs[mt + q + 8][ks + t * 2];
        unsigned a2 = *(unsigned*)&xs[mt + q][ks + t * 2 + 8];
        unsigned a3 = *(unsigned*)&xs[mt + q + 8][ks + t * 2 + 8];
        #pragma unroll
        for (int j = 0; j < 4; j++) {
            unsigned b0 = *(unsigned*)&ws[nq + j * 8 + q][ks + t * 2];
            unsigned b1 = *(unsigned*)&ws[nq + j * 8 + q][ks + t * 2 + 8];
            asm volatile(
                "mma.sync.aligned.m16n8k16.row.col.f32.f16.f16.f32 "
                "{%0,%1,%2,%3}, {%4,%5,%6,%7}, {%8,%9}, {%0,%1,%2,%3};"
                : "+f"(acc[j][0]), "+f"(acc[j][1]), "+f"(acc[j][2]), "+f"(acc[j][3])
                : "r"(a0), "r"(a1), "r"(a2), "r"(a3), "r"(b0), "r"(b1));
        }
    }

    int r0 = m0 + mt + q;
    int r1 = r0 + 8;
    float d0 = (r0 < n) ? g_dinv[r0] : 0.f;
    float d1 = (r1 < n) ? g_dinv[r1] : 0.f;
    unsigned char* T8 = (unsigned char*)g_t8;
    #pragma unroll
    for (int j = 0; j < 4; j++) {
        int col = nq + j * 8 + t * 2;
        if (r0 < n) {
            unsigned short u = f2_to_e4m3x2(acc[j][0] * d0, acc[j][1] * d0);
            *(unsigned short*)&T8[(long long)r0 * C + col] = u;
        }
        if (r1 < n) {
            unsigned short u = f2_to_e4m3x2(acc[j][2] * d1, acc[j][3] * d1);
            *(unsigned short*)&T8[(long long)r1 * C + col] = u;
        }
    }
}

// ---------------- CSR gather (fp8 messages, fp32 accum, MLP=16) ---------------
__global__ void k_gather(const float* __restrict__ bias, int n, int pool_mode) {
    int node = blockIdx.x * 8 + (threadIdx.x >> 5);
    int lane = threadIdx.x & 31;
    if (node >= n) return;
    int s = g_off[node], e = g_off[node + 1];

    const unsigned* T8 = g_t8;
    float4 acc = make_float4(0.f, 0.f, 0.f, 0.f);
    acc_fp8x4(acc, T8[node * C4 + lane]);   // self-loop term
    int i = s;
    for (; i + 16 <= e; i += 16) {
        unsigned v[16];
        #pragma unroll
        for (int k = 0; k < 16; k++) v[k] = T8[g_csr[i + k] * C4 + lane];
        #pragma unroll
        for (int k = 0; k < 16; k++) acc_fp8x4(acc, v[k]);
    }
    for (; i + 4 <= e; i += 4) {
        unsigned v0 = T8[g_csr[i]     * C4 + lane];
        unsigned v1 = T8[g_csr[i + 1] * C4 + lane];
        unsigned v2 = T8[g_csr[i + 2] * C4 + lane];
        unsigned v3 = T8[g_csr[i + 3] * C4 + lane];
        acc_fp8x4(acc, v0); acc_fp8x4(acc, v1);
        acc_fp8x4(acc, v2); acc_fp8x4(acc, v3);
    }
    for (; i < e; i++) acc_fp8x4(acc, T8[g_csr[i] * C4 + lane]);

    float di = g_dinv[node];
    float4 bv = ((const float4*)bias)[lane];
    float4 o;
    o.x = fmaxf(acc.x * di + bv.x, 0.f);
    o.y = fmaxf(acc.y * di + bv.y, 0.f);
    o.z = fmaxf(acc.z * di + bv.z, 0.f);
    o.w = fmaxf(acc.w * di + bv.w, 0.f);

    if (pool_mode) {
        int b = g_batch[node];
        atomicAdd(&g_pool4[b * C4 + lane], o);
    } else {
        __half2 h0 = __floats2half2_rn(o.x, o.y);
        __half2 h1 = __floats2half2_rn(o.z, o.w);
        uint2 p;
        p.x = *(unsigned*)&h0; p.y = *(unsigned*)&h1;
        ((uint2*)g_h16)[node * C4 + lane] = p;
    }
}

// ---------------- head --------------------------------------------------------
__global__ void k_head(const float* __restrict__ lin1_w,
                       const float* __restrict__ lin1_b,
                       const float* __restrict__ lin2_w,
                       const float* __restrict__ lin2_b,
                       float* __restrict__ out) {
    __shared__ float p[C];
    __shared__ float z1[LIN];
    __shared__ float z2[NCLS];
    int g = blockIdx.x;
    int tid = threadIdx.x;
    float cnt = g_cnt[g];
    if (cnt < 1.f) cnt = 1.f;
    if (tid < C) p[tid] = ((const float*)g_pool4)[g * C + tid] / cnt;
    __syncthreads();

    float acc = lin1_b[tid];
    for (int k = 0; k < C; k++) acc += p[k] * lin1_w[k * LIN + tid];
    z1[tid] = acc > 0.f ? acc : 0.f;
    __syncthreads();

    if (tid < NCLS) {
        float a = lin2_b[tid];
        for (int j = 0; j < LIN; j++) a += z1[j] * lin2_w[j * NCLS + tid];
        z2[tid] = a;
    }
    __syncthreads();

    if (tid == 0) {
        float m = z2[0];
        for (int k = 1; k < NCLS; k++) m = fmaxf(m, z2[k]);
        float s = 0.f;
        for (int k = 0; k < NCLS; k++) s += expf(z2[k] - m);
        float lse = m + logf(s);
        for (int k = 0; k < NCLS; k++) out[g * NCLS + k] = z2[k] - lse;
    }
}

__global__ void k_zero_out(float* out, int n) {
    int i = blockIdx.x * blockDim.x + threadIdx.x;
    if (i < n) out[i] = 0.f;
}

// ---------------- launch ------------------------------------------------------
extern "C" void kernel_launch(void* const* d_in, const int* in_sizes, int n_in,
                              void* d_out, int out_size) {
    const float* x      = (const float*)d_in[0];
    const void*  ei     = d_in[1];
    const void*  batch  = d_in[2];
    const float* W1     = (const float*)d_in[3];
    const float* b1     = (const float*)d_in[4];
    const float* W2     = (const float*)d_in[5];
    const float* b2     = (const float*)d_in[6];
    const float* W3     = (const float*)d_in[7];
    const float* b3     = (const float*)d_in[8];
    const float* lin1_w = (const float*)d_in[9];
    const float* lin1_b = (const float*)d_in[10];
    const float* lin2_w = (const float*)d_in[11];
    const float* lin2_b = (const float*)d_in[12];
    float* out = (float*)d_out;

    const int n = in_sizes[0] / C;          // 50000
    const int E = in_sizes[1] / 2;          // 1600000

    // ---- prep ----
    k_init<<<(n + 255) / 256, 256>>>((const int*)ei, n);
    k_edge_prep<<<(E + 255) / 256, 256>>>(ei, E, n);
    k_scan1<<<SCAN_NB, SCAN_BS>>>(n);
    k_scan2<<<1, 64>>>();
    k_scan3<<<(n + 256) / 256, 256>>>(n);
    k_fill<<<(E + 255) / 256, 256>>>(E, n);
    k_node_prep<<<(n + 255) / 256, 256>>>(batch, n);
    k_wt_all<<<(3 * C * C + 255) / 256, 256>>>(W1, W2, W3);

    // ---- 3 GCN layers ----
    const int mma_blocks  = (n + MB - 1) / MB;
    const int gath_blocks = (n + 7) / 8;
    const float* bs[3] = { b1, b2, b3 };
    for (int l = 0; l < 3; l++) {
        k_gemm_mma<<<mma_blocks, 256>>>(x, n, l);
        k_gather<<<gath_blocks, 256>>>(bs[l], n, l == 2 ? 1 : 0);
    }

    // ---- head ----
    if (out_size != NGRAPH * NCLS)
        k_zero_out<<<(out_size + 255) / 256, 256>>>(out, out_size);
    k_head<<<NGRAPH, LIN>>>(lin1_w, lin1_b, lin2_w, lin2_b, out);
}